// round 1
// baseline (speedup 1.0000x reference)
#include <cuda_runtime.h>
#include <math.h>

#define NH   4096
#define OBS  4096
#define OUT_N 4096
#define K2   (2*NH)     // 8192

// ---------------- persistent device scratch (no allocations) ----------------
__device__ float g_h[2][2][NH];     // [pingpong][batch][dim]
__device__ float g_u[2][NH];        // tanh hidden of f
__device__ float g_k[2][NH];        // current RK4 k
__device__ float g_ksum[2][NH];     // k1 + 2k2 + 2k3 + k4
__device__ float g_g[2][NH];        // GRU gate
__device__ float g_hfin[2][NH];     // h after ODE integration
__device__ float g_hhat[2][NH];     // GRU candidate
__device__ float g_hnew[2][NH];     // GRU output state (flat = concat(h_f, h_b))

// ---------------- warp dot helper: one warp, one row, batch-2 ----------------
template<int K4>
__device__ __forceinline__ void warp_dot2(const float4* __restrict__ Wr,
                                          const float4* __restrict__ v0,
                                          const float4* __restrict__ v1,
                                          int lane, float& a0, float& a1)
{
    a0 = 0.f; a1 = 0.f;
    #pragma unroll 8
    for (int i = lane; i < K4; i += 32) {
        float4 w  = Wr[i];
        float4 x0 = v0[i];
        float4 x1 = v1[i];
        a0 += w.x*x0.x + w.y*x0.y + w.z*x0.z + w.w*x0.w;
        a1 += w.x*x1.x + w.y*x1.y + w.z*x1.z + w.w*x1.w;
    }
    #pragma unroll
    for (int off = 16; off; off >>= 1) {
        a0 += __shfl_down_sync(0xffffffffu, a0, off);
        a1 += __shfl_down_sync(0xffffffffu, a1, off);
    }
}

// ---------------- f first layer: u = tanh(W1 @ v + b1) ----------------
// stage 0 (k1): v = h_prev + (dt_prev/6)*ksum  (= new base h; block 0 persists it)
// stage 1 (k2): v = h + 0.5*dt*k1
// stage 2 (k3): v = h + 0.5*dt*k2
// stage 3 (k4): v = h + dt*k3
__global__ __launch_bounds__(512)
void k_f1(const float* __restrict__ W, const float* __restrict__ bias,
          const float* __restrict__ tf, const float* __restrict__ tb,
          int s, int stage)
{
    __shared__ float sv[2][NH];
    const int tid = threadIdx.x;

    #pragma unroll
    for (int b = 0; b < 2; b++) {
        const float* t = b ? tb : tf;
        int rd; float cs = 0.f, ck = 0.f;
        if (stage == 0) {
            rd = s & 1;
            if (s > 0) cs = (t[s] - t[s-1]) * (1.0f/6.0f);
        } else {
            rd = (s + 1) & 1;
            const float dt = t[s+1] - t[s];
            ck = (stage == 3) ? dt : 0.5f * dt;
        }
        const float* hb = g_h[rd][b];
        for (int j = tid; j < NH; j += 512) {
            float v = hb[j];
            if (stage == 0) { if (s > 0) v += cs * g_ksum[b][j]; }
            else            { v += ck * g_k[b][j]; }
            sv[b][j] = v;
            if (stage == 0 && blockIdx.x == 0) g_h[(s + 1) & 1][b][j] = v;
        }
    }
    __syncthreads();

    const int warp = tid >> 5, lane = tid & 31;
    const int row  = blockIdx.x * 16 + warp;
    const float4* Wr = reinterpret_cast<const float4*>(W + (size_t)row * NH);
    float a0, a1;
    warp_dot2<NH/4>(Wr, reinterpret_cast<const float4*>(sv[0]),
                        reinterpret_cast<const float4*>(sv[1]), lane, a0, a1);
    if (lane == 0) {
        const float bb = bias[row];
        g_u[0][row] = tanhf(a0 + bb);
        g_u[1][row] = tanhf(a1 + bb);
    }
}

// ---------------- f second layer: k = W2 @ u + b2; ksum accumulation --------
__global__ __launch_bounds__(512)
void k_f2(const float* __restrict__ W, const float* __restrict__ bias, int stage)
{
    __shared__ float sv[2][NH];
    const int tid = threadIdx.x;
    for (int j = tid; j < NH; j += 512) { sv[0][j] = g_u[0][j]; sv[1][j] = g_u[1][j]; }
    __syncthreads();

    const int warp = tid >> 5, lane = tid & 31;
    const int row  = blockIdx.x * 16 + warp;
    const float4* Wr = reinterpret_cast<const float4*>(W + (size_t)row * NH);
    float a0, a1;
    warp_dot2<NH/4>(Wr, reinterpret_cast<const float4*>(sv[0]),
                        reinterpret_cast<const float4*>(sv[1]), lane, a0, a1);
    if (lane == 0) {
        const float bb = bias[row];
        const float k0 = a0 + bb, k1v = a1 + bb;
        g_k[0][row] = k0; g_k[1][row] = k1v;
        const float w = (stage == 1 || stage == 2) ? 2.f : 1.f;
        if (stage == 0) { g_ksum[0][row] = k0;         g_ksum[1][row] = k1v; }
        else            { g_ksum[0][row] += w * k0;    g_ksum[1][row] += w * k1v; }
    }
}

// ---------------- GRU matvec over i2h_W (4096 x 8192), batch 2 -------------
// phase 0: v = [x ; h_fin]          -> g = sigmoid(.)   (block 0 persists h_fin)
// phase 1: v = [x ; g .* h_fin]     -> h_hat = tanh(.)
__global__ __launch_bounds__(512)
void k_gru(const float* __restrict__ W, const float* __restrict__ bias,
           const float* __restrict__ xf, const float* __restrict__ xb,
           const float* __restrict__ tf, const float* __restrict__ tb,
           int nsteps, int phase)
{
    extern __shared__ float sv[];   // 2 * 8192 floats = 64 KB
    const int tid = threadIdx.x;
    const int base = nsteps & 1;

    #pragma unroll
    for (int b = 0; b < 2; b++) {
        const float* t = b ? tb : tf;
        const float* x = b ? xb : xf;
        float* v = sv + b * K2;
        for (int j = tid; j < NH; j += 512) v[j] = x[j];
        if (phase == 0) {
            const float cs = (t[nsteps] - t[nsteps-1]) * (1.0f/6.0f);
            for (int j = tid; j < NH; j += 512) {
                const float hf = g_h[base][b][j] + cs * g_ksum[b][j];
                v[NH + j] = hf;
                if (blockIdx.x == 0) g_hfin[b][j] = hf;
            }
        } else {
            for (int j = tid; j < NH; j += 512)
                v[NH + j] = g_g[b][j] * g_hfin[b][j];
        }
    }
    __syncthreads();

    const int warp = tid >> 5, lane = tid & 31;
    const int row  = blockIdx.x * 16 + warp;
    const float4* Wr = reinterpret_cast<const float4*>(W + (size_t)row * K2);
    float a0, a1;
    warp_dot2<K2/4>(Wr, reinterpret_cast<const float4*>(sv),
                        reinterpret_cast<const float4*>(sv + K2), lane, a0, a1);
    if (lane == 0) {
        const float bb = bias[row];
        const float r0 = a0 + bb, r1 = a1 + bb;
        if (phase == 0) {
            g_g[0][row] = 1.f / (1.f + expf(-r0));
            g_g[1][row] = 1.f / (1.f + expf(-r1));
        } else {
            g_hhat[0][row] = tanhf(r0);
            g_hhat[1][row] = tanhf(r1);
        }
    }
}

// ---------------- GRU blend + emit h_f / h_b to output ----------------------
__global__ void k_hnew(float* __restrict__ out)
{
    const int i = blockIdx.x * 256 + threadIdx.x;   // 0 .. 8191
    if (i < 2 * NH) {
        const int b = i >> 12, j = i & (NH - 1);
        const float g  = g_g[b][j];
        const float hn = g * g_hfin[b][j] + (1.f - g) * g_hhat[b][j];
        g_hnew[b][j] = hn;
        out[NH + i] = hn;    // out[4096..8191]=h_f, out[8192..12287]=h_b
    }
}

// ---------------- output matvec: out = h2o_W @ [h_f;h_b] + b ---------------
__global__ __launch_bounds__(512)
void k_out(const float* __restrict__ W, const float* __restrict__ bias,
           float* __restrict__ out)
{
    __shared__ float sv[K2];
    const int tid = threadIdx.x;
    const float* hflat = &g_hnew[0][0];
    for (int j = tid; j < K2; j += 512) sv[j] = hflat[j];
    __syncthreads();

    const int warp = tid >> 5, lane = tid & 31;
    const int row  = blockIdx.x * 16 + warp;
    const float4* Wr = reinterpret_cast<const float4*>(W + (size_t)row * K2);
    const float4* v  = reinterpret_cast<const float4*>(sv);
    float a = 0.f;
    #pragma unroll 8
    for (int i = lane; i < K2/4; i += 32) {
        float4 w = Wr[i]; float4 x = v[i];
        a += w.x*x.x + w.y*x.y + w.z*x.z + w.w*x.w;
    }
    #pragma unroll
    for (int off = 16; off; off >>= 1) a += __shfl_down_sync(0xffffffffu, a, off);
    if (lane == 0) out[row] = a + bias[row];
}

// ---------------- init: load h0 into ping-pong buffer 0 --------------------
__global__ void k_init(const float* __restrict__ hf, const float* __restrict__ hb)
{
    const int i = blockIdx.x * 256 + threadIdx.x;
    if (i < NH) { g_h[0][0][i] = hf[i]; g_h[0][1][i] = hb[i]; }
}

extern "C" void kernel_launch(void* const* d_in, const int* in_sizes, int n_in,
                              void* d_out, int out_size)
{
    const float* x_f   = (const float*)d_in[0];
    const float* x_b   = (const float*)d_in[1];
    const float* h_f   = (const float*)d_in[2];
    const float* h_b   = (const float*)d_in[3];
    const float* t_f   = (const float*)d_in[4];
    const float* t_b   = (const float*)d_in[5];
    const float* i2h_W = (const float*)d_in[6];
    const float* i2h_b = (const float*)d_in[7];
    const float* h2o_W = (const float*)d_in[8];
    const float* h2o_b = (const float*)d_in[9];
    const float* f_W1  = (const float*)d_in[10];
    const float* f_b1  = (const float*)d_in[11];
    const float* f_W2  = (const float*)d_in[12];
    const float* f_b2  = (const float*)d_in[13];
    float* out = (float*)d_out;

    const int T = in_sizes[4];       // 16
    const int nsteps = T - 1;        // 15

    // GRU kernel needs 64 KB dynamic smem
    cudaFuncSetAttribute((const void*)k_gru,
                         cudaFuncAttributeMaxDynamicSharedMemorySize, 2 * K2 * (int)sizeof(float));

    const dim3 GB(256), TB(512);     // 256 blocks x 16 rows = 4096 rows

    k_init<<<16, 256>>>(h_f, h_b);

    for (int s = 0; s < nsteps; s++) {
        #pragma unroll
        for (int stage = 0; stage < 4; stage++) {
            k_f1<<<GB, TB>>>(f_W1, f_b1, t_f, t_b, s, stage);
            k_f2<<<GB, TB>>>(f_W2, f_b2, stage);
        }
    }

    k_gru<<<GB, TB, 2 * K2 * sizeof(float)>>>(i2h_W, i2h_b, x_f, x_b, t_f, t_b, nsteps, 0);
    k_gru<<<GB, TB, 2 * K2 * sizeof(float)>>>(i2h_W, i2h_b, x_f, x_b, t_f, t_b, nsteps, 1);
    k_hnew<<<32, 256>>>(out);
    k_out<<<GB, TB>>>(h2o_W, h2o_b, out);
}

// round 2
// speedup vs baseline: 1.0070x; 1.0070x over previous
#include <cuda_runtime.h>
#include <cuda_fp16.h>
#include <math.h>

#define NH   4096
#define K2   (2*NH)     // 8192

// ---------------- persistent device scratch (no allocations) ----------------
__device__ __half g_W1h[(size_t)NH * NH];   // fp16 copy of f_W1 (32 MB)
__device__ __half g_W2h[(size_t)NH * NH];   // fp16 copy of f_W2 (32 MB)
__device__ float g_h[2][2][NH];     // [pingpong][batch][dim]
__device__ float g_u[2][NH];        // tanh hidden of f
__device__ float g_k[2][NH];        // current RK4 k
__device__ float g_ksum[2][NH];     // k1 + 2k2 + 2k3 + k4
__device__ float g_g[2][NH];        // GRU gate
__device__ float g_hfin[2][NH];     // h after ODE integration
__device__ float g_hhat[2][NH];     // GRU candidate
__device__ float g_hnew[2][NH];     // GRU output state (flat = concat(h_f, h_b))
__device__ float g_xd[2][NH];       // x-half dot of i2h_W (shared by both GRU phases)

// ---------------- fp32->fp16 weight conversion ----------------
__global__ __launch_bounds__(256)
void k_cvt(const float4* __restrict__ W, __half2* __restrict__ H, int n4)
{
    int i = blockIdx.x * 256 + threadIdx.x;
    if (i < n4) {
        float4 w = W[i];
        H[2*i]   = __floats2half2_rn(w.x, w.y);
        H[2*i+1] = __floats2half2_rn(w.z, w.w);
    }
}

// ---------------- warp dot, fp16 weights, batch-2 fp32 vectors --------------
__device__ __forceinline__ void warp_doth2(const uint4* __restrict__ Wr,
                                           const float4* __restrict__ v0,
                                           const float4* __restrict__ v1,
                                           int lane, float& a0, float& a1)
{
    a0 = 0.f; a1 = 0.f;
    #pragma unroll 4
    for (int i = lane; i < NH/8; i += 32) {     // 16 iterations
        uint4 w = Wr[i];
        float2 w0 = __half22float2(*reinterpret_cast<const __half2*>(&w.x));
        float2 w1 = __half22float2(*reinterpret_cast<const __half2*>(&w.y));
        float2 w2 = __half22float2(*reinterpret_cast<const __half2*>(&w.z));
        float2 w3 = __half22float2(*reinterpret_cast<const __half2*>(&w.w));
        float4 p = v0[2*i], q = v0[2*i+1];
        a0 += w0.x*p.x + w0.y*p.y + w1.x*p.z + w1.y*p.w
            + w2.x*q.x + w2.y*q.y + w3.x*q.z + w3.y*q.w;
        p = v1[2*i]; q = v1[2*i+1];
        a1 += w0.x*p.x + w0.y*p.y + w1.x*p.z + w1.y*p.w
            + w2.x*q.x + w2.y*q.y + w3.x*q.z + w3.y*q.w;
    }
    #pragma unroll
    for (int off = 16; off; off >>= 1) {
        a0 += __shfl_down_sync(0xffffffffu, a0, off);
        a1 += __shfl_down_sync(0xffffffffu, a1, off);
    }
}

// ---------------- warp dot, fp32 weights, batch-2 ----------------
template<int K4>
__device__ __forceinline__ void warp_dot2(const float4* __restrict__ Wr,
                                          const float4* __restrict__ v0,
                                          const float4* __restrict__ v1,
                                          int lane, float& a0, float& a1)
{
    a0 = 0.f; a1 = 0.f;
    #pragma unroll 8
    for (int i = lane; i < K4; i += 32) {
        float4 w  = Wr[i];
        float4 x0 = v0[i];
        float4 x1 = v1[i];
        a0 += w.x*x0.x + w.y*x0.y + w.z*x0.z + w.w*x0.w;
        a1 += w.x*x1.x + w.y*x1.y + w.z*x1.z + w.w*x1.w;
    }
    #pragma unroll
    for (int off = 16; off; off >>= 1) {
        a0 += __shfl_down_sync(0xffffffffu, a0, off);
        a1 += __shfl_down_sync(0xffffffffu, a1, off);
    }
}

// ---------------- f first layer: u = tanh(W1h @ v + b1) ----------------
// stage 0 (k1): v = h_prev + (dt_prev/6)*ksum  (= new base h; block 0 persists it)
// stage 1 (k2): v = h + 0.5*dt*k1
// stage 2 (k3): v = h + 0.5*dt*k2
// stage 3 (k4): v = h + dt*k3
__global__ __launch_bounds__(256)
void k_f1(const float* __restrict__ bias,
          const float* __restrict__ tf, const float* __restrict__ tb,
          int s, int stage)
{
    __shared__ float sv[2][NH];
    const int tid = threadIdx.x;

    #pragma unroll
    for (int b = 0; b < 2; b++) {
        const float* t = b ? tb : tf;
        int rd; float cs = 0.f, ck = 0.f;
        if (stage == 0) {
            rd = s & 1;
            if (s > 0) cs = (t[s] - t[s-1]) * (1.0f/6.0f);
        } else {
            rd = (s + 1) & 1;
            const float dt = t[s+1] - t[s];
            ck = (stage == 3) ? dt : 0.5f * dt;
        }
        const float* hb = g_h[rd][b];
        for (int j = tid; j < NH; j += 256) {
            float v = hb[j];
            if (stage == 0) { if (s > 0) v += cs * g_ksum[b][j]; }
            else            { v += ck * g_k[b][j]; }
            sv[b][j] = v;
            if (stage == 0 && blockIdx.x == 0) g_h[(s + 1) & 1][b][j] = v;
        }
    }
    __syncthreads();

    const int warp = tid >> 5, lane = tid & 31;
    const int row  = blockIdx.x * 8 + warp;
    const uint4* Wr = reinterpret_cast<const uint4*>(g_W1h + (size_t)row * NH);
    float a0, a1;
    warp_doth2(Wr, reinterpret_cast<const float4*>(sv[0]),
                   reinterpret_cast<const float4*>(sv[1]), lane, a0, a1);
    if (lane == 0) {
        const float bb = bias[row];
        g_u[0][row] = tanhf(a0 + bb);
        g_u[1][row] = tanhf(a1 + bb);
    }
}

// ---------------- f second layer: k = W2h @ u + b2; ksum accumulation -------
__global__ __launch_bounds__(256)
void k_f2(const float* __restrict__ bias, int stage)
{
    __shared__ float sv[2][NH];
    const int tid = threadIdx.x;
    for (int j = tid; j < NH; j += 256) { sv[0][j] = g_u[0][j]; sv[1][j] = g_u[1][j]; }
    __syncthreads();

    const int warp = tid >> 5, lane = tid & 31;
    const int row  = blockIdx.x * 8 + warp;
    const uint4* Wr = reinterpret_cast<const uint4*>(g_W2h + (size_t)row * NH);
    float a0, a1;
    warp_doth2(Wr, reinterpret_cast<const float4*>(sv[0]),
                   reinterpret_cast<const float4*>(sv[1]), lane, a0, a1);
    if (lane == 0) {
        const float bb = bias[row];
        const float k0 = a0 + bb, k1v = a1 + bb;
        g_k[0][row] = k0; g_k[1][row] = k1v;
        const float w = (stage == 1 || stage == 2) ? 2.f : 1.f;
        if (stage == 0) { g_ksum[0][row] = k0;         g_ksum[1][row] = k1v; }
        else            { g_ksum[0][row] += w * k0;    g_ksum[1][row] += w * k1v; }
    }
}

// ---------------- GRU x-half dot: xd = i2h_W[:, :NH] @ x  (shared by phases)
__global__ __launch_bounds__(256)
void k_xdot(const float* __restrict__ W,
            const float* __restrict__ xf, const float* __restrict__ xb)
{
    __shared__ float sv[2][NH];
    const int tid = threadIdx.x;
    for (int j = tid; j < NH; j += 256) { sv[0][j] = xf[j]; sv[1][j] = xb[j]; }
    __syncthreads();

    const int warp = tid >> 5, lane = tid & 31;
    const int row  = blockIdx.x * 8 + warp;
    const float4* Wr = reinterpret_cast<const float4*>(W + (size_t)row * K2);
    float a0, a1;
    warp_dot2<NH/4>(Wr, reinterpret_cast<const float4*>(sv[0]),
                        reinterpret_cast<const float4*>(sv[1]), lane, a0, a1);
    if (lane == 0) { g_xd[0][row] = a0; g_xd[1][row] = a1; }
}

// ---------------- GRU h-half matvec over i2h_W[:, NH:] ----------------------
// phase 0: v = h_fin               -> g = sigmoid(xd + . + b)  (block 0 persists h_fin)
// phase 1: v = g .* h_fin          -> h_hat = tanh(xd + . + b)
__global__ __launch_bounds__(256)
void k_gru(const float* __restrict__ W, const float* __restrict__ bias,
           const float* __restrict__ tf, const float* __restrict__ tb,
           int nsteps, int phase)
{
    __shared__ float sv[2][NH];
    const int tid = threadIdx.x;
    const int base = nsteps & 1;

    #pragma unroll
    for (int b = 0; b < 2; b++) {
        const float* t = b ? tb : tf;
        if (phase == 0) {
            const float cs = (t[nsteps] - t[nsteps-1]) * (1.0f/6.0f);
            for (int j = tid; j < NH; j += 256) {
                const float hf = g_h[base][b][j] + cs * g_ksum[b][j];
                sv[b][j] = hf;
                if (blockIdx.x == 0) g_hfin[b][j] = hf;
            }
        } else {
            for (int j = tid; j < NH; j += 256)
                sv[b][j] = g_g[b][j] * g_hfin[b][j];
        }
    }
    __syncthreads();

    const int warp = tid >> 5, lane = tid & 31;
    const int row  = blockIdx.x * 8 + warp;
    const float4* Wr = reinterpret_cast<const float4*>(W + (size_t)row * K2 + NH);
    float a0, a1;
    warp_dot2<NH/4>(Wr, reinterpret_cast<const float4*>(sv[0]),
                        reinterpret_cast<const float4*>(sv[1]), lane, a0, a1);
    if (lane == 0) {
        const float bb = bias[row];
        const float r0 = g_xd[0][row] + a0 + bb;
        const float r1 = g_xd[1][row] + a1 + bb;
        if (phase == 0) {
            g_g[0][row] = 1.f / (1.f + expf(-r0));
            g_g[1][row] = 1.f / (1.f + expf(-r1));
        } else {
            g_hhat[0][row] = tanhf(r0);
            g_hhat[1][row] = tanhf(r1);
        }
    }
}

// ---------------- GRU blend + emit h_f / h_b to output ----------------------
__global__ void k_hnew(float* __restrict__ out)
{
    const int i = blockIdx.x * 256 + threadIdx.x;   // 0 .. 8191
    if (i < 2 * NH) {
        const int b = i >> 12, j = i & (NH - 1);
        const float g  = g_g[b][j];
        const float hn = g * g_hfin[b][j] + (1.f - g) * g_hhat[b][j];
        g_hnew[b][j] = hn;
        out[NH + i] = hn;    // out[4096..8191]=h_f, out[8192..12287]=h_b
    }
}

// ---------------- output matvec: out = h2o_W @ [h_f;h_b] + b ---------------
__global__ __launch_bounds__(256)
void k_out(const float* __restrict__ W, const float* __restrict__ bias,
           float* __restrict__ out)
{
    __shared__ float sv[K2];
    const int tid = threadIdx.x;
    const float* hflat = &g_hnew[0][0];
    for (int j = tid; j < K2; j += 256) sv[j] = hflat[j];
    __syncthreads();

    const int warp = tid >> 5, lane = tid & 31;
    const int row  = blockIdx.x * 8 + warp;
    const float4* Wr = reinterpret_cast<const float4*>(W + (size_t)row * K2);
    const float4* v  = reinterpret_cast<const float4*>(sv);
    float a = 0.f;
    #pragma unroll 8
    for (int i = lane; i < K2/4; i += 32) {
        float4 w = Wr[i]; float4 x = v[i];
        a += w.x*x.x + w.y*x.y + w.z*x.z + w.w*x.w;
    }
    #pragma unroll
    for (int off = 16; off; off >>= 1) a += __shfl_down_sync(0xffffffffu, a, off);
    if (lane == 0) out[row] = a + bias[row];
}

// ---------------- init: load h0 into ping-pong buffer 0 --------------------
__global__ void k_init(const float* __restrict__ hf, const float* __restrict__ hb)
{
    const int i = blockIdx.x * 256 + threadIdx.x;
    if (i < NH) { g_h[0][0][i] = hf[i]; g_h[0][1][i] = hb[i]; }
}

extern "C" void kernel_launch(void* const* d_in, const int* in_sizes, int n_in,
                              void* d_out, int out_size)
{
    const float* x_f   = (const float*)d_in[0];
    const float* x_b   = (const float*)d_in[1];
    const float* h_f   = (const float*)d_in[2];
    const float* h_b   = (const float*)d_in[3];
    const float* t_f   = (const float*)d_in[4];
    const float* t_b   = (const float*)d_in[5];
    const float* i2h_W = (const float*)d_in[6];
    const float* i2h_b = (const float*)d_in[7];
    const float* h2o_W = (const float*)d_in[8];
    const float* h2o_b = (const float*)d_in[9];
    const float* f_W1  = (const float*)d_in[10];
    const float* f_b1  = (const float*)d_in[11];
    const float* f_W2  = (const float*)d_in[12];
    const float* f_b2  = (const float*)d_in[13];
    float* out = (float*)d_out;

    const int T = in_sizes[4];       // 16
    const int nsteps = T - 1;        // 15

    const int n4 = NH * NH / 4;                 // float4 count per weight matrix
    const int cvtGrid = (n4 + 255) / 256;

    __half *w1h_dev, *w2h_dev;
    cudaGetSymbolAddress((void**)&w1h_dev, g_W1h);
    cudaGetSymbolAddress((void**)&w2h_dev, g_W2h);

    k_cvt<<<cvtGrid, 256>>>((const float4*)f_W1, (__half2*)w1h_dev, n4);
    k_cvt<<<cvtGrid, 256>>>((const float4*)f_W2, (__half2*)w2h_dev, n4);
    k_init<<<16, 256>>>(h_f, h_b);

    const dim3 GB(512), TB(256);     // 512 blocks x 8 rows = 4096 rows

    // x-half dot of the GRU is independent of the ODE — do it up front.
    k_xdot<<<GB, TB>>>(i2h_W, x_f, x_b);

    for (int s = 0; s < nsteps; s++) {
        #pragma unroll
        for (int stage = 0; stage < 4; stage++) {
            k_f1<<<GB, TB>>>(f_b1, t_f, t_b, s, stage);
            k_f2<<<GB, TB>>>(f_b2, stage);
        }
    }

    k_gru<<<GB, TB>>>(i2h_W, i2h_b, t_f, t_b, nsteps, 0);
    k_gru<<<GB, TB>>>(i2h_W, i2h_b, t_f, t_b, nsteps, 1);
    k_hnew<<<32, 256>>>(out);
    k_out<<<GB, TB>>>(h2o_W, h2o_b, out);
}

// round 3
// speedup vs baseline: 1.9910x; 1.9772x over previous
#include <cuda_runtime.h>
#include <cuda_fp16.h>
#include <math.h>

#define NH     4096
#define K2     8192
#define GRIDB  128          // blocks (<= SM count -> guaranteed co-resident)
#define TPB    1024         // threads per block (32 warps)
#define ROWS_PB 32          // rows per block per matvec pass (1 row per warp)

// ---------------- persistent device scratch (no allocations) ----------------
__device__ __half g_W1h[(size_t)NH * NH];   // fp16 f_W1 (32 MB)
__device__ __half g_W2h[(size_t)NH * NH];   // fp16 f_W2 (32 MB)
__device__ float  g_h[2][2][NH];            // [pingpong][batch][dim]
__device__ __half g_uh[2][NH];              // tanh hidden of f (fp16)
__device__ float  g_k[2][NH];               // current RK4 k
__device__ float  g_ksum[2][NH];            // k1 + 2k2 + 2k3 + k4
__device__ float  g_g[2][NH];               // GRU gate
__device__ float  g_hfin[2][NH];            // h after ODE integration
__device__ float  g_hhat[2][NH];            // GRU candidate
__device__ float  g_hnew[2][NH];            // GRU output state
__device__ float  g_xd[2][NH];              // x-half dot of i2h_W
__device__ unsigned g_arrive;               // grid barrier counter

// ---------------- barrier reset (runs once per graph replay) ----------------
__global__ void k_reset() { g_arrive = 0u; }

// ---------------- fp32 -> fp16 weight conversion ----------------
__global__ __launch_bounds__(256)
void k_cvt(const float4* __restrict__ W, __half2* __restrict__ H, int n4)
{
    int i = blockIdx.x * 256 + threadIdx.x;
    if (i < n4) {
        float4 w = W[i];
        H[2*i]   = __floats2half2_rn(w.x, w.y);
        H[2*i+1] = __floats2half2_rn(w.z, w.w);
    }
}

// ---------------- grid barrier: monotonic counter, no reset races -----------
__device__ __forceinline__ void gbar(unsigned& target)
{
    __syncthreads();
    if (threadIdx.x == 0) {
        __threadfence();                       // release (and L1 flush on sm_103a)
        atomicAdd(&g_arrive, 1u);
        volatile unsigned* p = &g_arrive;
        while (*p < target) { __nanosleep(64); }
        __threadfence();                       // acquire: invalidate L1 before reads
    }
    __syncthreads();
    target += GRIDB;
}

// ---------------- warp dot, fp16 weights + fp16 v, fp32 accum, batch-2 ------
__device__ __forceinline__ void wdot_h(const __half* __restrict__ Wrow,
                                       const __half* __restrict__ v0,
                                       const __half* __restrict__ v1,
                                       int lane, float& a0, float& a1)
{
    const uint4* W4 = reinterpret_cast<const uint4*>(Wrow);
    const uint4* V0 = reinterpret_cast<const uint4*>(v0);
    const uint4* V1 = reinterpret_cast<const uint4*>(v1);
    a0 = 0.f; a1 = 0.f;
    #pragma unroll 2
    for (int i = lane; i < NH/8; i += 32) {      // 16 iterations
        uint4 w = W4[i], p = V0[i], q = V1[i];
        const __half2* wh = reinterpret_cast<const __half2*>(&w);
        const __half2* ph = reinterpret_cast<const __half2*>(&p);
        const __half2* qh = reinterpret_cast<const __half2*>(&q);
        #pragma unroll
        for (int t = 0; t < 4; t++) {
            float2 wf = __half22float2(wh[t]);
            float2 pf = __half22float2(ph[t]);
            float2 qf = __half22float2(qh[t]);
            a0 = fmaf(wf.x, pf.x, a0); a0 = fmaf(wf.y, pf.y, a0);
            a1 = fmaf(wf.x, qf.x, a1); a1 = fmaf(wf.y, qf.y, a1);
        }
    }
    #pragma unroll
    for (int off = 16; off; off >>= 1) {
        a0 += __shfl_down_sync(0xffffffffu, a0, off);
        a1 += __shfl_down_sync(0xffffffffu, a1, off);
    }
}

// ---------------- warp dot, fp32 weights, batch-2 ----------------
template<int K4>
__device__ __forceinline__ void wdot_f2(const float4* __restrict__ Wr,
                                        const float4* __restrict__ v0,
                                        const float4* __restrict__ v1,
                                        int lane, float& a0, float& a1)
{
    a0 = 0.f; a1 = 0.f;
    #pragma unroll 4
    for (int i = lane; i < K4; i += 32) {
        float4 w = Wr[i], x0 = v0[i], x1 = v1[i];
        a0 += w.x*x0.x + w.y*x0.y + w.z*x0.z + w.w*x0.w;
        a1 += w.x*x1.x + w.y*x1.y + w.z*x1.z + w.w*x1.w;
    }
    #pragma unroll
    for (int off = 16; off; off >>= 1) {
        a0 += __shfl_down_sync(0xffffffffu, a0, off);
        a1 += __shfl_down_sync(0xffffffffu, a1, off);
    }
}

// ---------------- warp dot, fp32 weights, batch-1 ----------------
template<int K4>
__device__ __forceinline__ float wdot_f1(const float4* __restrict__ Wr,
                                         const float4* __restrict__ v,
                                         int lane)
{
    float a = 0.f;
    #pragma unroll 4
    for (int i = lane; i < K4; i += 32) {
        float4 w = Wr[i], x = v[i];
        a += w.x*x.x + w.y*x.y + w.z*x.z + w.w*x.w;
    }
    #pragma unroll
    for (int off = 16; off; off >>= 1) a += __shfl_down_sync(0xffffffffu, a, off);
    return a;
}

// ---------------- the whole model in one persistent kernel ------------------
__global__ __launch_bounds__(TPB, 1)
void k_all(const float* __restrict__ f_b1, const float* __restrict__ f_b2,
           const float* __restrict__ i2h_W, const float* __restrict__ i2h_b,
           const float* __restrict__ h2o_W, const float* __restrict__ h2o_b,
           const float* __restrict__ x_f, const float* __restrict__ x_b,
           const float* __restrict__ h_f, const float* __restrict__ h_b,
           const float* __restrict__ tf, const float* __restrict__ tb,
           float* __restrict__ out, int nsteps)
{
    __shared__ __half svh[2][NH];   // 16 KB: fp16 vector for ODE matvecs
    __shared__ float  svf[2][NH];   // 32 KB: fp32 vector for GRU/out matvecs

    const int tid  = threadIdx.x;
    const int warp = tid >> 5, lane = tid & 31;
    const int row  = blockIdx.x * ROWS_PB + warp;
    unsigned target = GRIDB;

    // ---- init h0 (partitioned across grid) ----
    {
        int gidx = blockIdx.x * TPB + tid;
        if (gidx < NH) { g_h[0][0][gidx] = h_f[gidx]; g_h[0][1][gidx] = h_b[gidx]; }
    }

    // ---- GRU x-half dot (independent of ODE): xd = i2h_W[:, :NH] @ x ----
    for (int j = tid; j < NH; j += TPB) { svf[0][j] = x_f[j]; svf[1][j] = x_b[j]; }
    __syncthreads();
    {
        float a0, a1;
        wdot_f2<NH/4>(reinterpret_cast<const float4*>(i2h_W + (size_t)row * K2),
                      reinterpret_cast<const float4*>(svf[0]),
                      reinterpret_cast<const float4*>(svf[1]), lane, a0, a1);
        if (lane == 0) { g_xd[0][row] = a0; g_xd[1][row] = a1; }
    }
    gbar(target);   // also publishes h0 init

    // ---- RK4 ODE: 15 steps x 4 stages x 2 layers ----
    for (int s = 0; s < nsteps; s++) {
        for (int stage = 0; stage < 4; stage++) {
            // f layer 1: v per stage, u = tanh(W1h @ v + b1)
            #pragma unroll
            for (int b = 0; b < 2; b++) {
                const float* t = b ? tb : tf;
                int rd; float cs = 0.f, ck = 0.f;
                if (stage == 0) {
                    rd = s & 1;
                    if (s > 0) cs = (t[s] - t[s-1]) * (1.0f/6.0f);
                } else {
                    rd = (s + 1) & 1;
                    const float dt = t[s+1] - t[s];
                    ck = (stage == 3) ? dt : 0.5f * dt;
                }
                const float* hb = g_h[rd][b];
                for (int j = tid; j < NH; j += TPB) {
                    float v = hb[j];
                    if (stage == 0) { if (s > 0) v += cs * g_ksum[b][j]; }
                    else            { v += ck * g_k[b][j]; }
                    svh[b][j] = __float2half(v);
                    if (stage == 0 && blockIdx.x == 0) g_h[(s + 1) & 1][b][j] = v;
                }
            }
            __syncthreads();
            {
                float a0, a1;
                wdot_h(g_W1h + (size_t)row * NH, svh[0], svh[1], lane, a0, a1);
                if (lane == 0) {
                    const float bb = f_b1[row];
                    g_uh[0][row] = __float2half(tanhf(a0 + bb));
                    g_uh[1][row] = __float2half(tanhf(a1 + bb));
                }
            }
            gbar(target);

            // f layer 2: k = W2h @ u + b2; ksum accumulation
            {
                const uint4* U0 = reinterpret_cast<const uint4*>(g_uh[0]);
                const uint4* U1 = reinterpret_cast<const uint4*>(g_uh[1]);
                uint4* S0 = reinterpret_cast<uint4*>(svh[0]);
                uint4* S1 = reinterpret_cast<uint4*>(svh[1]);
                for (int i = tid; i < NH/8; i += TPB) { S0[i] = U0[i]; S1[i] = U1[i]; }
            }
            __syncthreads();
            {
                float a0, a1;
                wdot_h(g_W2h + (size_t)row * NH, svh[0], svh[1], lane, a0, a1);
                if (lane == 0) {
                    const float bb = f_b2[row];
                    const float k0 = a0 + bb, k1v = a1 + bb;
                    g_k[0][row] = k0; g_k[1][row] = k1v;
                    const float w = (stage == 1 || stage == 2) ? 2.f : 1.f;
                    if (stage == 0) { g_ksum[0][row] = k0;      g_ksum[1][row] = k1v; }
                    else            { g_ksum[0][row] += w * k0; g_ksum[1][row] += w * k1v; }
                }
            }
            gbar(target);
        }
    }

    // ---- GRU phase 0: g = sigmoid(xd + W_h @ h_fin + b) ----
    {
        const int base = nsteps & 1;
        #pragma unroll
        for (int b = 0; b < 2; b++) {
            const float* t = b ? tb : tf;
            const float cs = (t[nsteps] - t[nsteps-1]) * (1.0f/6.0f);
            for (int j = tid; j < NH; j += TPB) {
                const float hf = g_h[base][b][j] + cs * g_ksum[b][j];
                svf[b][j] = hf;
                if (blockIdx.x == 0) g_hfin[b][j] = hf;
            }
        }
        __syncthreads();
        float a0, a1;
        wdot_f2<NH/4>(reinterpret_cast<const float4*>(i2h_W + (size_t)row * K2 + NH),
                      reinterpret_cast<const float4*>(svf[0]),
                      reinterpret_cast<const float4*>(svf[1]), lane, a0, a1);
        if (lane == 0) {
            const float bb = i2h_b[row];
            g_g[0][row] = 1.f / (1.f + expf(-(g_xd[0][row] + a0 + bb)));
            g_g[1][row] = 1.f / (1.f + expf(-(g_xd[1][row] + a1 + bb)));
        }
    }
    gbar(target);

    // ---- GRU phase 1: h_hat = tanh(xd + W_h @ (g .* h_fin) + b) ----
    {
        #pragma unroll
        for (int b = 0; b < 2; b++)
            for (int j = tid; j < NH; j += TPB)
                svf[b][j] = g_g[b][j] * g_hfin[b][j];
        __syncthreads();
        float a0, a1;
        wdot_f2<NH/4>(reinterpret_cast<const float4*>(i2h_W + (size_t)row * K2 + NH),
                      reinterpret_cast<const float4*>(svf[0]),
                      reinterpret_cast<const float4*>(svf[1]), lane, a0, a1);
        if (lane == 0) {
            const float bb = i2h_b[row];
            g_hhat[0][row] = tanhf(g_xd[0][row] + a0 + bb);
            g_hhat[1][row] = tanhf(g_xd[1][row] + a1 + bb);
        }
    }
    gbar(target);

    // ---- GRU blend + emit h_f / h_b ----
    {
        int i = blockIdx.x * TPB + tid;
        if (i < 2 * NH) {
            const int b = i >> 12, j = i & (NH - 1);
            const float g  = g_g[b][j];
            const float hn = g * g_hfin[b][j] + (1.f - g) * g_hhat[b][j];
            g_hnew[b][j] = hn;
            out[NH + i] = hn;
        }
    }
    gbar(target);

    // ---- output matvec: out = h2o_W @ [h_f;h_b] + b ----
    {
        const float* hflat = &g_hnew[0][0];
        float* sflat = &svf[0][0];
        for (int j = tid; j < K2; j += TPB) sflat[j] = hflat[j];
        __syncthreads();
        float a = wdot_f1<K2/4>(reinterpret_cast<const float4*>(h2o_W + (size_t)row * K2),
                                reinterpret_cast<const float4*>(sflat), lane);
        if (lane == 0) out[row] = a + h2o_b[row];
    }
}

extern "C" void kernel_launch(void* const* d_in, const int* in_sizes, int n_in,
                              void* d_out, int out_size)
{
    const float* x_f   = (const float*)d_in[0];
    const float* x_b   = (const float*)d_in[1];
    const float* h_f   = (const float*)d_in[2];
    const float* h_b   = (const float*)d_in[3];
    const float* t_f   = (const float*)d_in[4];
    const float* t_b   = (const float*)d_in[5];
    const float* i2h_W = (const float*)d_in[6];
    const float* i2h_b = (const float*)d_in[7];
    const float* h2o_W = (const float*)d_in[8];
    const float* h2o_b = (const float*)d_in[9];
    const float* f_W1  = (const float*)d_in[10];
    const float* f_b1  = (const float*)d_in[11];
    const float* f_W2  = (const float*)d_in[12];
    const float* f_b2  = (const float*)d_in[13];
    float* out = (float*)d_out;

    const int T = in_sizes[4];
    const int nsteps = T - 1;

    const int n4 = NH * NH / 4;
    const int cvtGrid = (n4 + 255) / 256;

    __half *w1h_dev, *w2h_dev;
    cudaGetSymbolAddress((void**)&w1h_dev, g_W1h);
    cudaGetSymbolAddress((void**)&w2h_dev, g_W2h);

    k_cvt<<<cvtGrid, 256>>>((const float4*)f_W1, (__half2*)w1h_dev, n4);
    k_cvt<<<cvtGrid, 256>>>((const float4*)f_W2, (__half2*)w2h_dev, n4);
    k_reset<<<1, 1>>>();

    k_all<<<GRIDB, TPB>>>(f_b1, f_b2, i2h_W, i2h_b, h2o_W, h2o_b,
                          x_f, x_b, h_f, h_b, t_f, t_b, out, nsteps);
}

// round 4
// speedup vs baseline: 2.7478x; 1.3801x over previous
#include <cuda_runtime.h>
#include <cuda_fp16.h>
#include <math.h>
#include <stdint.h>

#define NH     4096
#define K2     8192
#define GRIDB  128          // blocks (<= 148 SMs -> co-resident, barrier safe)
#define TPB    1024         // 32 warps
#define ROWS_PB 32          // rows per block per matvec

// ---------------- persistent device scratch (no allocations) ----------------
__device__ __half g_W1p[(size_t)NH * NH];   // fp16 f_W1, fragment-major (32 MB)
__device__ __half g_W2p[(size_t)NH * NH];   // fp16 f_W2, fragment-major (32 MB)
__device__ float  g_h[2][2][NH];            // [pingpong][batch][dim]
__device__ __half g_uh[2][NH];              // tanh hidden of f (fp16)
__device__ float  g_k[2][NH];               // current RK4 k
__device__ float  g_ksum[2][NH];            // k1 + 2k2 + 2k3 + k4
__device__ float  g_g[2][NH];               // GRU gate
__device__ float  g_hfin[2][NH];            // h after ODE integration
__device__ float  g_hhat[2][NH];            // GRU candidate
__device__ float  g_hnew[2][NH];            // GRU output state
__device__ float  g_xd[2][NH];              // x-half dot of i2h_W
__device__ unsigned g_arrive;               // grid barrier counter

__global__ void k_reset() { g_arrive = 0u; }

// ------- fp32 -> fp16 + permute to mma A-fragment-major layout --------------
// Tile (rg, kt) covers rows rg*16..+15, cols kt*16..+15. Stored as 32 lanes x
// 16 B, lane l = {W[R0+g][C0+2q..+1], W[R0+8+g][C0+2q..], W[R0+g][C0+8+2q..],
// W[R0+8+g][C0+8+2q..]} with g=l/4, q=l%4 (the m16n8k16 row-major A image).
__global__ __launch_bounds__(256)
void k_perm(const float* __restrict__ W, __half* __restrict__ P)
{
    const int gidx = blockIdx.x * 256 + threadIdx.x;   // tile*32 + lane
    const int lane = gidx & 31, tile = gidx >> 5;
    const int rg = tile >> 8, kt = tile & 255;
    const int R0 = rg * 16, C0 = kt * 16;
    const int g = lane >> 2, q = lane & 3;
    const float2* r0p = reinterpret_cast<const float2*>(W + (size_t)(R0 + g)     * NH + C0 + 2*q);
    const float2* r8p = reinterpret_cast<const float2*>(W + (size_t)(R0 + 8 + g) * NH + C0 + 2*q);
    float2 a01 = r0p[0];
    float2 a23 = r8p[0];
    float2 a45 = r0p[4];    // +8 columns
    float2 a67 = r8p[4];
    __half2 h0 = __floats2half2_rn(a01.x, a01.y);
    __half2 h1 = __floats2half2_rn(a23.x, a23.y);
    __half2 h2 = __floats2half2_rn(a45.x, a45.y);
    __half2 h3 = __floats2half2_rn(a67.x, a67.y);
    uint4 o;
    o.x = *reinterpret_cast<uint32_t*>(&h0);
    o.y = *reinterpret_cast<uint32_t*>(&h1);
    o.z = *reinterpret_cast<uint32_t*>(&h2);
    o.w = *reinterpret_cast<uint32_t*>(&h3);
    reinterpret_cast<uint4*>(P)[gidx] = o;
}

// ---------------- grid barrier: monotonic counter ----------------
__device__ __forceinline__ void gbar(unsigned& target)
{
    __syncthreads();
    if (threadIdx.x == 0) {
        __threadfence();
        atomicAdd(&g_arrive, 1u);
        volatile unsigned* p = &g_arrive;
        while (*p < target) { __nanosleep(32); }
        __threadfence();
    }
    __syncthreads();
    target += GRIDB;
}

// ---------------- HMMA m16n8k16 fp32-accum ----------------
__device__ __forceinline__ void mma16816(float c[4], const uint4& a,
                                         uint32_t b0, uint32_t b1)
{
    asm volatile(
        "mma.sync.aligned.m16n8k16.row.col.f32.f16.f16.f32 "
        "{%0,%1,%2,%3}, {%4,%5,%6,%7}, {%8,%9}, {%0,%1,%2,%3};"
        : "+f"(c[0]), "+f"(c[1]), "+f"(c[2]), "+f"(c[3])
        : "r"(a.x), "r"(a.y), "r"(a.z), "r"(a.w), "r"(b0), "r"(b1));
}

// ODE matvec: block computes rows [blockIdx*32, +32) against full K=4096.
// 32 warps = 2 row-groups x 16 K-chunks (256 each). Partials -> smem -> reduce.
__device__ __forceinline__ void ode_mv(const __half* __restrict__ Wp,
                                       const __half (*svh)[NH],
                                       float* __restrict__ part,
                                       int warp, int lane)
{
    const int rg = warp >> 4;            // 0..1
    const int kc = warp & 15;            // 0..15
    const int rg_glob = blockIdx.x * 2 + rg;
    const uint4* A = reinterpret_cast<const uint4*>(Wp)
                   + ((size_t)rg_glob * 256 + kc * 16) * 32 + lane;
    const int n = lane >> 2, q = lane & 3;
    const bool hasB = (n < 2);
    const __half* vb = svh[hasB ? n : 0];
    const int K0 = kc * 256 + q * 2;

    float c[4] = {0.f, 0.f, 0.f, 0.f};
    #pragma unroll 4
    for (int s = 0; s < 16; s++) {
        uint4 a = A[(size_t)s * 32];
        uint32_t b0 = 0u, b1 = 0u;
        if (hasB) {
            b0 = *reinterpret_cast<const uint32_t*>(vb + K0 + s * 16);
            b1 = *reinterpret_cast<const uint32_t*>(vb + K0 + s * 16 + 8);
        }
        mma16816(c, a, b0, b1);
    }
    if (q == 0) {
        const int r = rg * 16 + (lane >> 2);       // local row 0..31 (r and r+8)
        part[(kc * 32 + r)     * 2 + 0] = c[0];
        part[(kc * 32 + r)     * 2 + 1] = c[1];
        part[(kc * 32 + r + 8) * 2 + 0] = c[2];
        part[(kc * 32 + r + 8) * 2 + 1] = c[3];
    }
}

// ---------------- fp32 warp dots (GRU / out, run once) ----------------
template<int K4>
__device__ __forceinline__ void wdot_f2(const float4* __restrict__ Wr,
                                        const float4* __restrict__ v0,
                                        const float4* __restrict__ v1,
                                        int lane, float& a0, float& a1)
{
    a0 = 0.f; a1 = 0.f;
    #pragma unroll 4
    for (int i = lane; i < K4; i += 32) {
        float4 w = Wr[i], x0 = v0[i], x1 = v1[i];
        a0 += w.x*x0.x + w.y*x0.y + w.z*x0.z + w.w*x0.w;
        a1 += w.x*x1.x + w.y*x1.y + w.z*x1.z + w.w*x1.w;
    }
    #pragma unroll
    for (int off = 16; off; off >>= 1) {
        a0 += __shfl_down_sync(0xffffffffu, a0, off);
        a1 += __shfl_down_sync(0xffffffffu, a1, off);
    }
}

template<int K4>
__device__ __forceinline__ float wdot_f1(const float4* __restrict__ Wr,
                                         const float4* __restrict__ v, int lane)
{
    float a = 0.f;
    #pragma unroll 4
    for (int i = lane; i < K4; i += 32) {
        float4 w = Wr[i], x = v[i];
        a += w.x*x.x + w.y*x.y + w.z*x.z + w.w*x.w;
    }
    #pragma unroll
    for (int off = 16; off; off >>= 1) a += __shfl_down_sync(0xffffffffu, a, off);
    return a;
}

// ---------------- the whole model in one persistent kernel ------------------
__global__ __launch_bounds__(TPB, 1)
void k_all(const float* __restrict__ f_b1, const float* __restrict__ f_b2,
           const float* __restrict__ i2h_W, const float* __restrict__ i2h_b,
           const float* __restrict__ h2o_W, const float* __restrict__ h2o_b,
           const float* __restrict__ x_f, const float* __restrict__ x_b,
           const float* __restrict__ h_f, const float* __restrict__ h_b,
           const float* __restrict__ tf, const float* __restrict__ tb,
           float* __restrict__ out, int nsteps)
{
    __shared__ __half svh[2][NH];          // 16 KB: fp16 v for ODE mma
    __shared__ union {
        float svf[2][NH];                  // 32 KB: fp32 v (GRU / out phases)
        float part[16 * 32 * 2];           //  4 KB: mma partials (ODE phases)
    } sm;

    const int tid  = threadIdx.x;
    const int warp = tid >> 5, lane = tid & 31;
    const int row  = blockIdx.x * ROWS_PB + warp;
    unsigned target = GRIDB;

    // ---- init h0 ----
    {
        int gidx = blockIdx.x * TPB + tid;
        if (gidx < NH) { g_h[0][0][gidx] = h_f[gidx]; g_h[0][1][gidx] = h_b[gidx]; }
    }

    // ---- GRU x-half dot (independent of ODE) ----
    for (int j = tid; j < NH; j += TPB) { sm.svf[0][j] = x_f[j]; sm.svf[1][j] = x_b[j]; }
    __syncthreads();
    {
        float a0, a1;
        wdot_f2<NH/4>(reinterpret_cast<const float4*>(i2h_W + (size_t)row * K2),
                      reinterpret_cast<const float4*>(sm.svf[0]),
                      reinterpret_cast<const float4*>(sm.svf[1]), lane, a0, a1);
        if (lane == 0) { g_xd[0][row] = a0; g_xd[1][row] = a1; }
    }
    gbar(target);   // also publishes h0

    // ---- RK4 ODE ----
    for (int s = 0; s < nsteps; s++) {
        for (int stage = 0; stage < 4; stage++) {
            // ---- layer 1: v prep -> svh ----
            #pragma unroll
            for (int b = 0; b < 2; b++) {
                const float* t = b ? tb : tf;
                int rd; float cs = 0.f, ck = 0.f;
                if (stage == 0) {
                    rd = s & 1;
                    if (s > 0) cs = (t[s] - t[s-1]) * (1.0f/6.0f);
                } else {
                    rd = (s + 1) & 1;
                    const float dt = t[s+1] - t[s];
                    ck = (stage == 3) ? dt : 0.5f * dt;
                }
                const float* hb = g_h[rd][b];
                for (int j = tid; j < NH; j += TPB) {
                    float v = hb[j];
                    if (stage == 0) { if (s > 0) v += cs * g_ksum[b][j]; }
                    else            { v += ck * g_k[b][j]; }
                    svh[b][j] = __float2half(v);
                    if (stage == 0 && blockIdx.x == 0) g_h[(s + 1) & 1][b][j] = v;
                }
            }
            __syncthreads();
            ode_mv(g_W1p, svh, sm.part, warp, lane);
            __syncthreads();
            if (tid < 64) {
                const int r = tid >> 1, b = tid & 1;
                float acc = 0.f;
                #pragma unroll
                for (int kc = 0; kc < 16; kc++) acc += sm.part[(kc * 32 + r) * 2 + b];
                const int rw = blockIdx.x * ROWS_PB + r;
                g_uh[b][rw] = __float2half(tanhf(acc + f_b1[rw]));
            }
            gbar(target);

            // ---- layer 2: u -> svh ----
            {
                const uint4* U = reinterpret_cast<const uint4*>(&g_uh[0][0]);
                uint4* S = reinterpret_cast<uint4*>(&svh[0][0]);
                for (int i = tid; i < 2 * NH / 8; i += TPB) S[i] = U[i];
            }
            __syncthreads();
            ode_mv(g_W2p, svh, sm.part, warp, lane);
            __syncthreads();
            if (tid < 64) {
                const int r = tid >> 1, b = tid & 1;
                float acc = 0.f;
                #pragma unroll
                for (int kc = 0; kc < 16; kc++) acc += sm.part[(kc * 32 + r) * 2 + b];
                const int rw = blockIdx.x * ROWS_PB + r;
                const float kv = acc + f_b2[rw];
                g_k[b][rw] = kv;
                const float w = (stage == 1 || stage == 2) ? 2.f : 1.f;
                if (stage == 0) g_ksum[b][rw] = kv;
                else            g_ksum[b][rw] += w * kv;
            }
            gbar(target);
        }
    }

    // ---- GRU phase 0 ----
    {
        const int base = nsteps & 1;
        #pragma unroll
        for (int b = 0; b < 2; b++) {
            const float* t = b ? tb : tf;
            const float cs = (t[nsteps] - t[nsteps-1]) * (1.0f/6.0f);
            for (int j = tid; j < NH; j += TPB) {
                const float hf = g_h[base][b][j] + cs * g_ksum[b][j];
                sm.svf[b][j] = hf;
                if (blockIdx.x == 0) g_hfin[b][j] = hf;
            }
        }
        __syncthreads();
        float a0, a1;
        wdot_f2<NH/4>(reinterpret_cast<const float4*>(i2h_W + (size_t)row * K2 + NH),
                      reinterpret_cast<const float4*>(sm.svf[0]),
                      reinterpret_cast<const float4*>(sm.svf[1]), lane, a0, a1);
        if (lane == 0) {
            const float bb = i2h_b[row];
            g_g[0][row] = 1.f / (1.f + expf(-(g_xd[0][row] + a0 + bb)));
            g_g[1][row] = 1.f / (1.f + expf(-(g_xd[1][row] + a1 + bb)));
        }
    }
    gbar(target);

    // ---- GRU phase 1 ----
    {
        #pragma unroll
        for (int b = 0; b < 2; b++)
            for (int j = tid; j < NH; j += TPB)
                sm.svf[b][j] = g_g[b][j] * g_hfin[b][j];
        __syncthreads();
        float a0, a1;
        wdot_f2<NH/4>(reinterpret_cast<const float4*>(i2h_W + (size_t)row * K2 + NH),
                      reinterpret_cast<const float4*>(sm.svf[0]),
                      reinterpret_cast<const float4*>(sm.svf[1]), lane, a0, a1);
        if (lane == 0) {
            const float bb = i2h_b[row];
            g_hhat[0][row] = tanhf(g_xd[0][row] + a0 + bb);
            g_hhat[1][row] = tanhf(g_xd[1][row] + a1 + bb);
        }
    }
    gbar(target);

    // ---- GRU blend ----
    {
        int i = blockIdx.x * TPB + tid;
        if (i < 2 * NH) {
            const int b = i >> 12, j = i & (NH - 1);
            const float g  = g_g[b][j];
            const float hn = g * g_hfin[b][j] + (1.f - g) * g_hhat[b][j];
            g_hnew[b][j] = hn;
            out[NH + i] = hn;
        }
    }
    gbar(target);

    // ---- output matvec ----
    {
        const float* hflat = &g_hnew[0][0];
        float* sflat = &sm.svf[0][0];
        for (int j = tid; j < K2; j += TPB) sflat[j] = hflat[j];
        __syncthreads();
        float a = wdot_f1<K2/4>(reinterpret_cast<const float4*>(h2o_W + (size_t)row * K2),
                                reinterpret_cast<const float4*>(sflat), lane);
        if (lane == 0) out[row] = a + h2o_b[row];
    }
}

extern "C" void kernel_launch(void* const* d_in, const int* in_sizes, int n_in,
                              void* d_out, int out_size)
{
    const float* x_f   = (const float*)d_in[0];
    const float* x_b   = (const float*)d_in[1];
    const float* h_f   = (const float*)d_in[2];
    const float* h_b   = (const float*)d_in[3];
    const float* t_f   = (const float*)d_in[4];
    const float* t_b   = (const float*)d_in[5];
    const float* i2h_W = (const float*)d_in[6];
    const float* i2h_b = (const float*)d_in[7];
    const float* h2o_W = (const float*)d_in[8];
    const float* h2o_b = (const float*)d_in[9];
    const float* f_W1  = (const float*)d_in[10];
    const float* f_b1  = (const float*)d_in[11];
    const float* f_W2  = (const float*)d_in[12];
    const float* f_b2  = (const float*)d_in[13];
    float* out = (float*)d_out;

    const int T = in_sizes[4];
    const int nsteps = T - 1;

    __half *w1p, *w2p;
    cudaGetSymbolAddress((void**)&w1p, g_W1p);
    cudaGetSymbolAddress((void**)&w2p, g_W2p);

    const int permBlocks = (NH / 16) * (NH / 16) * 32 / 256;   // 8192
    k_perm<<<permBlocks, 256>>>(f_W1, w1p);
    k_perm<<<permBlocks, 256>>>(f_W2, w2p);
    k_reset<<<1, 1>>>();

    k_all<<<GRIDB, TPB>>>(f_b1, f_b2, i2h_W, i2h_b, h2o_W, h2o_b,
                          x_f, x_b, h_f, h_b, t_f, t_b, out, nsteps);
}

// round 5
// speedup vs baseline: 3.1441x; 1.1442x over previous
#include <cuda_runtime.h>
#include <cuda_fp16.h>
#include <math.h>
#include <stdint.h>

#define NH     4096
#define K2     8192
#define GRIDB  128          // blocks (<= 148 SMs -> co-resident, barrier safe)
#define TPB    512          // 16 warps
#define ROWS_PB 32

// ---------------- persistent device scratch (no allocations) ----------------
__device__ __half g_W1p[(size_t)NH * NH];   // fp16 f_W1, fragment-major
__device__ __half g_W2p[(size_t)NH * NH];   // fp16 f_W2, fragment-major
__device__ float  g_h[2][2][NH];
__device__ __half g_uh[2][NH];
__device__ float  g_k[2][NH];
__device__ float  g_ksum[2][NH];
__device__ float  g_g[2][NH];
__device__ float  g_hfin[2][NH];
__device__ float  g_hhat[2][NH];
__device__ float  g_hnew[2][NH];
__device__ float  g_xd[2][NH];
__device__ unsigned g_arrive;

__global__ void k_reset() { g_arrive = 0u; }

// ------- fp32 -> fp16 + permute to mma A-fragment-major layout --------------
__global__ __launch_bounds__(256)
void k_perm(const float* __restrict__ W, __half* __restrict__ P)
{
    const int gidx = blockIdx.x * 256 + threadIdx.x;   // tile*32 + lane
    const int lane = gidx & 31, tile = gidx >> 5;
    const int rg = tile >> 8, kt = tile & 255;
    const int R0 = rg * 16, C0 = kt * 16;
    const int g = lane >> 2, q = lane & 3;
    const float2* r0p = reinterpret_cast<const float2*>(W + (size_t)(R0 + g)     * NH + C0 + 2*q);
    const float2* r8p = reinterpret_cast<const float2*>(W + (size_t)(R0 + 8 + g) * NH + C0 + 2*q);
    float2 a01 = r0p[0];
    float2 a23 = r8p[0];
    float2 a45 = r0p[4];
    float2 a67 = r8p[4];
    __half2 h0 = __floats2half2_rn(a01.x, a01.y);
    __half2 h1 = __floats2half2_rn(a23.x, a23.y);
    __half2 h2 = __floats2half2_rn(a45.x, a45.y);
    __half2 h3 = __floats2half2_rn(a67.x, a67.y);
    uint4 o;
    o.x = *reinterpret_cast<uint32_t*>(&h0);
    o.y = *reinterpret_cast<uint32_t*>(&h1);
    o.z = *reinterpret_cast<uint32_t*>(&h2);
    o.w = *reinterpret_cast<uint32_t*>(&h3);
    reinterpret_cast<uint4*>(P)[gidx] = o;
}

// ---------------- split grid barrier ----------------
__device__ __forceinline__ void bar_arrive()
{
    __syncthreads();
    if (threadIdx.x == 0) {
        __threadfence();                 // release: publish this block's writes
        atomicAdd(&g_arrive, 1u);
    }
}
__device__ __forceinline__ void bar_wait(unsigned& target)
{
    if (threadIdx.x == 0) {
        volatile unsigned* p = &g_arrive;
        while (*p < target) {}
        __threadfence();                 // acquire: CCTL.IVALL before reads
    }
    __syncthreads();
    target += GRIDB;
}

// ---------------- HMMA m16n8k16 fp32-accum ----------------
__device__ __forceinline__ void mma16816(float c[4], const uint4& a,
                                         uint32_t b0, uint32_t b1)
{
    asm volatile(
        "mma.sync.aligned.m16n8k16.row.col.f32.f16.f16.f32 "
        "{%0,%1,%2,%3}, {%4,%5,%6,%7}, {%8,%9}, {%0,%1,%2,%3};"
        : "+f"(c[0]), "+f"(c[1]), "+f"(c[2]), "+f"(c[3])
        : "r"(a.x), "r"(a.y), "r"(a.z), "r"(a.w), "r"(b0), "r"(b1));
}

// A-fragment pointer for this warp (16 warps = 2 rg x 8 kc, 32 steps each)
__device__ __forceinline__ const uint4* a_ptr(const __half* Wp, int warp, int lane)
{
    const int rg = warp >> 3, kc = warp & 7;
    const int rg_glob = blockIdx.x * 2 + rg;
    return reinterpret_cast<const uint4*>(Wp)
         + ((size_t)rg_glob * 256 + kc * 32) * 32 + lane;
}

__device__ __forceinline__ void a_prefetch(uint4* abuf, const uint4* A)
{
    #pragma unroll
    for (int p = 0; p < 8; p++) abuf[p] = A[p * 32];
}

// mma mainloop: ring buffer 8 deep, 2 accumulator chains, 32 steps (K=512)
__device__ __forceinline__ void ode_mma(uint4* abuf, const uint4* A,
                                        const __half (*svh)[NH],
                                        float* __restrict__ part,
                                        int warp, int lane)
{
    const int rg = warp >> 3, kc = warp & 7;
    const int n = lane >> 2, q = lane & 3;
    const bool hasB = (n < 2);
    const __half* vb = svh[hasB ? n : 0];
    const int K0 = kc * 512 + q * 2;

    float c0[4] = {0.f,0.f,0.f,0.f}, c1[4] = {0.f,0.f,0.f,0.f};
    #pragma unroll
    for (int s = 0; s < 32; s++) {
        uint4 a = abuf[s & 7];
        if (s < 24) abuf[s & 7] = A[(size_t)(s + 8) * 32];
        uint32_t b0 = 0u, b1 = 0u;
        if (hasB) {
            b0 = *reinterpret_cast<const uint32_t*>(vb + K0 + s * 16);
            b1 = *reinterpret_cast<const uint32_t*>(vb + K0 + s * 16 + 8);
        }
        if (s & 1) mma16816(c1, a, b0, b1);
        else       mma16816(c0, a, b0, b1);
    }
    if (q == 0) {
        const int r = rg * 16 + n;
        part[(kc * 32 + r)     * 2 + 0] = c0[0] + c1[0];
        part[(kc * 32 + r)     * 2 + 1] = c0[1] + c1[1];
        part[(kc * 32 + r + 8) * 2 + 0] = c0[2] + c1[2];
        part[(kc * 32 + r + 8) * 2 + 1] = c0[3] + c1[3];
    }
}

// ---------------- fp32 warp dots (GRU / out) ----------------
template<int K4>
__device__ __forceinline__ void wdot_f2(const float4* __restrict__ Wr,
                                        const float4* __restrict__ v0,
                                        const float4* __restrict__ v1,
                                        int lane, float& a0, float& a1)
{
    a0 = 0.f; a1 = 0.f;
    #pragma unroll 8
    for (int i = lane; i < K4; i += 32) {
        float4 w = Wr[i], x0 = v0[i], x1 = v1[i];
        a0 += w.x*x0.x + w.y*x0.y + w.z*x0.z + w.w*x0.w;
        a1 += w.x*x1.x + w.y*x1.y + w.z*x1.z + w.w*x1.w;
    }
    #pragma unroll
    for (int off = 16; off; off >>= 1) {
        a0 += __shfl_down_sync(0xffffffffu, a0, off);
        a1 += __shfl_down_sync(0xffffffffu, a1, off);
    }
}

template<int K4>
__device__ __forceinline__ float wdot_f1(const float4* __restrict__ Wr,
                                         const float4* __restrict__ v, int lane)
{
    float a = 0.f;
    #pragma unroll 8
    for (int i = lane; i < K4; i += 32) {
        float4 w = Wr[i], x = v[i];
        a += w.x*x.x + w.y*x.y + w.z*x.z + w.w*x.w;
    }
    #pragma unroll
    for (int off = 16; off; off >>= 1) a += __shfl_down_sync(0xffffffffu, a, off);
    return a;
}

// ---------------- the whole model in one persistent kernel ------------------
__global__ __launch_bounds__(TPB, 1)
void k_all(const float* __restrict__ f_b1, const float* __restrict__ f_b2,
           const float* __restrict__ i2h_W, const float* __restrict__ i2h_b,
           const float* __restrict__ h2o_W, const float* __restrict__ h2o_b,
           const float* __restrict__ x_f, const float* __restrict__ x_b,
           const float* __restrict__ h_f, const float* __restrict__ h_b,
           const float* __restrict__ tf, const float* __restrict__ tb,
           float* __restrict__ out, int nsteps)
{
    __shared__ __half svh[2][NH];          // 16 KB
    __shared__ union {
        float svf[2][NH];                  // 32 KB (GRU / out)
        float part[8 * 32 * 2];            //  2 KB (ODE partials)
    } sm;

    const int tid  = threadIdx.x;
    const int warp = tid >> 5, lane = tid & 31;
    unsigned target = GRIDB;
    uint4 abuf[8];

    // ---- init h0 ----
    {
        int gidx = blockIdx.x * TPB + tid;
        if (gidx < NH) { g_h[0][0][gidx] = h_f[gidx]; g_h[0][1][gidx] = h_b[gidx]; }
    }

    // ---- GRU x-half dot (independent of ODE) ----
    for (int j = tid; j < NH; j += TPB) { sm.svf[0][j] = x_f[j]; sm.svf[1][j] = x_b[j]; }
    __syncthreads();
    #pragma unroll
    for (int r2 = 0; r2 < 2; r2++) {
        const int row = blockIdx.x * ROWS_PB + warp * 2 + r2;
        float a0, a1;
        wdot_f2<NH/4>(reinterpret_cast<const float4*>(i2h_W + (size_t)row * K2),
                      reinterpret_cast<const float4*>(sm.svf[0]),
                      reinterpret_cast<const float4*>(sm.svf[1]), lane, a0, a1);
        if (lane == 0) { g_xd[0][row] = a0; g_xd[1][row] = a1; }
    }
    bar_arrive();

    // ---- RK4 ODE: 120 phases ----
    for (int s = 0; s < nsteps; s++) {
        for (int stage = 0; stage < 4; stage++) {
            // ======== layer 1 ========
            const uint4* A1 = a_ptr(g_W1p, warp, lane);
            a_prefetch(abuf, A1);           // overlaps barrier wait
            bar_wait(target);
            // v-prep (vectorized)
            #pragma unroll
            for (int b = 0; b < 2; b++) {
                const float* t = b ? tb : tf;
                int rd; float cf = 0.f; int mode;  // 0: none, 1: +cf*ksum, 2: +cf*k
                if (stage == 0) {
                    rd = s & 1;
                    if (s > 0) { cf = (t[s] - t[s-1]) * (1.0f/6.0f); mode = 1; }
                    else mode = 0;
                } else {
                    rd = (s + 1) & 1;
                    const float dt = t[s+1] - t[s];
                    cf = (stage == 3) ? dt : 0.5f * dt; mode = 2;
                }
                const float4* hb4  = reinterpret_cast<const float4*>(g_h[rd][b]);
                const float4* aux4 = reinterpret_cast<const float4*>(mode == 1 ? g_ksum[b] : g_k[b]);
                __half2* sh2 = reinterpret_cast<__half2*>(svh[b]);
                float4* hw4 = reinterpret_cast<float4*>(g_h[(s + 1) & 1][b]);
                for (int j = tid; j < NH/4; j += TPB) {
                    float4 v = hb4[j];
                    if (mode) {
                        float4 x = aux4[j];
                        v.x += cf * x.x; v.y += cf * x.y;
                        v.z += cf * x.z; v.w += cf * x.w;
                    }
                    sh2[2*j]   = __floats2half2_rn(v.x, v.y);
                    sh2[2*j+1] = __floats2half2_rn(v.z, v.w);
                    if (stage == 0 && blockIdx.x == 0) hw4[j] = v;
                }
            }
            __syncthreads();
            ode_mma(abuf, A1, svh, sm.part, warp, lane);
            __syncthreads();
            if (tid < 64) {
                const int r = tid >> 1, b = tid & 1;
                float acc = 0.f;
                #pragma unroll
                for (int kc = 0; kc < 8; kc++) acc += sm.part[(kc * 32 + r) * 2 + b];
                const int rw = blockIdx.x * ROWS_PB + r;
                g_uh[b][rw] = __float2half(tanhf(acc + f_b1[rw]));
            }
            bar_arrive();

            // ======== layer 2 ========
            const uint4* A2 = a_ptr(g_W2p, warp, lane);
            a_prefetch(abuf, A2);
            bar_wait(target);
            {
                const uint4* U = reinterpret_cast<const uint4*>(&g_uh[0][0]);
                uint4* S = reinterpret_cast<uint4*>(&svh[0][0]);
                for (int i = tid; i < 2 * NH / 8; i += TPB) S[i] = U[i];
            }
            __syncthreads();
            ode_mma(abuf, A2, svh, sm.part, warp, lane);
            __syncthreads();
            if (tid < 64) {
                const int r = tid >> 1, b = tid & 1;
                float acc = 0.f;
                #pragma unroll
                for (int kc = 0; kc < 8; kc++) acc += sm.part[(kc * 32 + r) * 2 + b];
                const int rw = blockIdx.x * ROWS_PB + r;
                const float kv = acc + f_b2[rw];
                g_k[b][rw] = kv;
                const float w = (stage == 1 || stage == 2) ? 2.f : 1.f;
                if (stage == 0) g_ksum[b][rw] = kv;
                else            g_ksum[b][rw] += w * kv;
            }
            bar_arrive();
        }
    }

    // ---- GRU phase 0 ----
    bar_wait(target);
    {
        const int base = nsteps & 1;
        #pragma unroll
        for (int b = 0; b < 2; b++) {
            const float* t = b ? tb : tf;
            const float cs = (t[nsteps] - t[nsteps-1]) * (1.0f/6.0f);
            for (int j = tid; j < NH; j += TPB) {
                const float hf = g_h[base][b][j] + cs * g_ksum[b][j];
                sm.svf[b][j] = hf;
                if (blockIdx.x == 0) g_hfin[b][j] = hf;
            }
        }
        __syncthreads();
        #pragma unroll
        for (int r2 = 0; r2 < 2; r2++) {
            const int row = blockIdx.x * ROWS_PB + warp * 2 + r2;
            float a0, a1;
            wdot_f2<NH/4>(reinterpret_cast<const float4*>(i2h_W + (size_t)row * K2 + NH),
                          reinterpret_cast<const float4*>(sm.svf[0]),
                          reinterpret_cast<const float4*>(sm.svf[1]), lane, a0, a1);
            if (lane == 0) {
                const float bb = i2h_b[row];
                g_g[0][row] = 1.f / (1.f + expf(-(g_xd[0][row] + a0 + bb)));
                g_g[1][row] = 1.f / (1.f + expf(-(g_xd[1][row] + a1 + bb)));
            }
        }
    }
    bar_arrive();

    // ---- GRU phase 1 ----
    bar_wait(target);
    {
        #pragma unroll
        for (int b = 0; b < 2; b++)
            for (int j = tid; j < NH; j += TPB)
                sm.svf[b][j] = g_g[b][j] * g_hfin[b][j];
        __syncthreads();
        #pragma unroll
        for (int r2 = 0; r2 < 2; r2++) {
            const int row = blockIdx.x * ROWS_PB + warp * 2 + r2;
            float a0, a1;
            wdot_f2<NH/4>(reinterpret_cast<const float4*>(i2h_W + (size_t)row * K2 + NH),
                          reinterpret_cast<const float4*>(sm.svf[0]),
                          reinterpret_cast<const float4*>(sm.svf[1]), lane, a0, a1);
            if (lane == 0) {
                const float bb = i2h_b[row];
                g_hhat[0][row] = tanhf(g_xd[0][row] + a0 + bb);
                g_hhat[1][row] = tanhf(g_xd[1][row] + a1 + bb);
            }
        }
    }
    bar_arrive();

    // ---- GRU blend ----
    bar_wait(target);
    {
        int i = blockIdx.x * TPB + tid;
        if (i < 2 * NH) {
            const int b = i >> 12, j = i & (NH - 1);
            const float g  = g_g[b][j];
            const float hn = g * g_hfin[b][j] + (1.f - g) * g_hhat[b][j];
            g_hnew[b][j] = hn;
            out[NH + i] = hn;
        }
    }
    bar_arrive();

    // ---- output matvec ----
    bar_wait(target);
    {
        const float* hflat = &g_hnew[0][0];
        float* sflat = &sm.svf[0][0];
        for (int j = tid; j < K2; j += TPB) sflat[j] = hflat[j];
        __syncthreads();
        #pragma unroll
        for (int r2 = 0; r2 < 2; r2++) {
            const int row = blockIdx.x * ROWS_PB + warp * 2 + r2;
            float a = wdot_f1<K2/4>(reinterpret_cast<const float4*>(h2o_W + (size_t)row * K2),
                                    reinterpret_cast<const float4*>(sflat), lane);
            if (lane == 0) out[row] = a + h2o_b[row];
        }
    }
}

extern "C" void kernel_launch(void* const* d_in, const int* in_sizes, int n_in,
                              void* d_out, int out_size)
{
    const float* x_f   = (const float*)d_in[0];
    const float* x_b   = (const float*)d_in[1];
    const float* h_f   = (const float*)d_in[2];
    const float* h_b   = (const float*)d_in[3];
    const float* t_f   = (const float*)d_in[4];
    const float* t_b   = (const float*)d_in[5];
    const float* i2h_W = (const float*)d_in[6];
    const float* i2h_b = (const float*)d_in[7];
    const float* h2o_W = (const float*)d_in[8];
    const float* h2o_b = (const float*)d_in[9];
    const float* f_W1  = (const float*)d_in[10];
    const float* f_b1  = (const float*)d_in[11];
    const float* f_W2  = (const float*)d_in[12];
    const float* f_b2  = (const float*)d_in[13];
    float* out = (float*)d_out;

    const int T = in_sizes[4];
    const int nsteps = T - 1;

    __half *w1p, *w2p;
    cudaGetSymbolAddress((void**)&w1p, g_W1p);
    cudaGetSymbolAddress((void**)&w2p, g_W2p);

    const int permBlocks = (NH / 16) * (NH / 16) * 32 / 256;   // 8192
    k_perm<<<permBlocks, 256>>>(f_W1, w1p);
    k_perm<<<permBlocks, 256>>>(f_W2, w2p);
    k_reset<<<1, 1>>>();

    k_all<<<GRIDB, TPB>>>(f_b1, f_b2, i2h_W, i2h_b, h2o_W, h2o_b,
                          x_f, x_b, h_f, h_b, t_f, t_b, out, nsteps);
}

// round 6
// speedup vs baseline: 3.8821x; 1.2347x over previous
#include <cuda_runtime.h>
#include <cuda_fp16.h>
#include <math.h>
#include <stdint.h>

#define NH     4096
#define K2     8192
#define GRIDB  128          // blocks (<= 148 SMs -> co-resident, barrier safe)
#define TPB    512          // 16 warps
#define ROWS_PB 32

// ---------------- persistent device scratch (no allocations) ----------------
__device__ __half g_W1p[(size_t)NH * NH];   // fp16 f_W1, fragment-major
__device__ __half g_W2p[(size_t)NH * NH];   // fp16 f_W2, fragment-major
__device__ __half g_vh[2][NH];              // current ODE input vector v (fp16)
__device__ __half g_uh[2][NH];              // tanh hidden u (fp16)
__device__ float  g_vfin[2][NH];            // h after full integration (fp32)
__device__ float  g_g[2][NH];
__device__ float  g_hhat[2][NH];
__device__ float  g_hnew[2][NH];
__device__ float  g_xd[2][NH];
__device__ unsigned g_arrive;

__global__ void k_reset() { g_arrive = 0u; }

// ------- fp32 -> fp16 + permute to mma A-fragment-major layout --------------
__global__ __launch_bounds__(256)
void k_perm(const float* __restrict__ W, __half* __restrict__ P)
{
    const int gidx = blockIdx.x * 256 + threadIdx.x;   // tile*32 + lane
    const int lane = gidx & 31, tile = gidx >> 5;
    const int rg = tile >> 8, kt = tile & 255;
    const int R0 = rg * 16, C0 = kt * 16;
    const int g = lane >> 2, q = lane & 3;
    const float2* r0p = reinterpret_cast<const float2*>(W + (size_t)(R0 + g)     * NH + C0 + 2*q);
    const float2* r8p = reinterpret_cast<const float2*>(W + (size_t)(R0 + 8 + g) * NH + C0 + 2*q);
    float2 a01 = r0p[0];
    float2 a23 = r8p[0];
    float2 a45 = r0p[4];
    float2 a67 = r8p[4];
    __half2 h0 = __floats2half2_rn(a01.x, a01.y);
    __half2 h1 = __floats2half2_rn(a23.x, a23.y);
    __half2 h2 = __floats2half2_rn(a45.x, a45.y);
    __half2 h3 = __floats2half2_rn(a67.x, a67.y);
    uint4 o;
    o.x = *reinterpret_cast<uint32_t*>(&h0);
    o.y = *reinterpret_cast<uint32_t*>(&h1);
    o.z = *reinterpret_cast<uint32_t*>(&h2);
    o.w = *reinterpret_cast<uint32_t*>(&h3);
    reinterpret_cast<uint4*>(P)[gidx] = o;
}

// ---------------- light grid barrier: release-red / acquire-poll ------------
// Cross-block data travels via .cg (L2-only) accesses, so no L1 flush needed.
__device__ __forceinline__ void bar_arrive()
{
    __syncthreads();
    if (threadIdx.x == 0) {
        unsigned* p = &g_arrive;
        asm volatile("red.release.gpu.global.add.u32 [%0], 1;" :: "l"(p) : "memory");
    }
}
__device__ __forceinline__ void bar_wait(unsigned& target)
{
    if (threadIdx.x == 0) {
        unsigned* p = &g_arrive;
        unsigned v;
        do {
            asm volatile("ld.acquire.gpu.global.u32 %0, [%1];" : "=r"(v) : "l"(p) : "memory");
        } while (v < target);
    }
    __syncthreads();
    target += GRIDB;
}

// ---------------- HMMA m16n8k16 fp32-accum ----------------
__device__ __forceinline__ void mma16816(float c[4], const uint4& a,
                                         uint32_t b0, uint32_t b1)
{
    asm volatile(
        "mma.sync.aligned.m16n8k16.row.col.f32.f16.f16.f32 "
        "{%0,%1,%2,%3}, {%4,%5,%6,%7}, {%8,%9}, {%0,%1,%2,%3};"
        : "+f"(c[0]), "+f"(c[1]), "+f"(c[2]), "+f"(c[3])
        : "r"(a.x), "r"(a.y), "r"(a.z), "r"(a.w), "r"(b0), "r"(b1));
}

__device__ __forceinline__ const uint4* a_ptr(const __half* Wp, int warp, int lane)
{
    const int rg = warp >> 3, kc = warp & 7;
    const int rg_glob = blockIdx.x * 2 + rg;
    return reinterpret_cast<const uint4*>(Wp)
         + ((size_t)rg_glob * 256 + kc * 32) * 32 + lane;
}

__device__ __forceinline__ void a_prefetch(uint4* abuf, const uint4* A)
{
    #pragma unroll
    for (int p = 0; p < 8; p++) abuf[p] = A[p * 32];
}

// mma mainloop: ring 8, 2 accumulator chains, 32 steps (K=512 per warp)
__device__ __forceinline__ void ode_mma(uint4* abuf, const uint4* A,
                                        const __half* __restrict__ svh,   // [2][NH] flat
                                        float* __restrict__ part,
                                        int warp, int lane)
{
    const int rg = warp >> 3, kc = warp & 7;
    const int n = lane >> 2, q = lane & 3;
    const bool hasB = (n < 2);
    const __half* vb = svh + (hasB ? n : 0) * NH;
    const int K0 = kc * 512 + q * 2;

    float c0[4] = {0.f,0.f,0.f,0.f}, c1[4] = {0.f,0.f,0.f,0.f};
    #pragma unroll
    for (int s = 0; s < 32; s++) {
        uint4 a = abuf[s & 7];
        if (s < 24) abuf[s & 7] = A[(size_t)(s + 8) * 32];
        uint32_t b0 = 0u, b1 = 0u;
        if (hasB) {
            b0 = *reinterpret_cast<const uint32_t*>(vb + K0 + s * 16);
            b1 = *reinterpret_cast<const uint32_t*>(vb + K0 + s * 16 + 8);
        }
        if (s & 1) mma16816(c1, a, b0, b1);
        else       mma16816(c0, a, b0, b1);
    }
    if (q == 0) {
        const int r = rg * 16 + n;
        part[(kc * 32 + r)     * 2 + 0] = c0[0] + c1[0];
        part[(kc * 32 + r)     * 2 + 1] = c0[1] + c1[1];
        part[(kc * 32 + r + 8) * 2 + 0] = c0[2] + c1[2];
        part[(kc * 32 + r + 8) * 2 + 1] = c0[3] + c1[3];
    }
}

// ---------------- fp32 warp dots (GRU / out) ----------------
template<int K4>
__device__ __forceinline__ void wdot_f2(const float4* __restrict__ Wr,
                                        const float4* __restrict__ v0,
                                        const float4* __restrict__ v1,
                                        int lane, float& a0, float& a1)
{
    a0 = 0.f; a1 = 0.f;
    #pragma unroll 8
    for (int i = lane; i < K4; i += 32) {
        float4 w = Wr[i], x0 = v0[i], x1 = v1[i];
        a0 += w.x*x0.x + w.y*x0.y + w.z*x0.z + w.w*x0.w;
        a1 += w.x*x1.x + w.y*x1.y + w.z*x1.z + w.w*x1.w;
    }
    #pragma unroll
    for (int off = 16; off; off >>= 1) {
        a0 += __shfl_down_sync(0xffffffffu, a0, off);
        a1 += __shfl_down_sync(0xffffffffu, a1, off);
    }
}

template<int K4>
__device__ __forceinline__ float wdot_f1(const float4* __restrict__ Wr,
                                         const float4* __restrict__ v, int lane)
{
    float a = 0.f;
    #pragma unroll 8
    for (int i = lane; i < K4; i += 32) {
        float4 w = Wr[i], x = v[i];
        a += w.x*x.x + w.y*x.y + w.z*x.z + w.w*x.w;
    }
    #pragma unroll
    for (int off = 16; off; off >>= 1) a += __shfl_down_sync(0xffffffffu, a, off);
    return a;
}

// ---------------- the whole model in one persistent kernel ------------------
__global__ __launch_bounds__(TPB, 1)
void k_all(const float* __restrict__ f_b1, const float* __restrict__ f_b2,
           const float* __restrict__ i2h_W, const float* __restrict__ i2h_b,
           const float* __restrict__ h2o_W, const float* __restrict__ h2o_b,
           const float* __restrict__ x_f, const float* __restrict__ x_b,
           const float* __restrict__ h_f, const float* __restrict__ h_b,
           const float* __restrict__ tf, const float* __restrict__ tb,
           float* __restrict__ out, int nsteps)
{
    __shared__ __half svh[2 * NH];         // 16 KB (ODE v / u staging)
    __shared__ union {
        float svf[2][NH];                  // 32 KB (GRU / out)
        float part[8 * 32 * 2];            //  2 KB (ODE partials)
    } sm;

    const int tid  = threadIdx.x;
    const int warp = tid >> 5, lane = tid & 31;
    unsigned target = GRIDB;
    uint4 abuf[8];

    // ---- reducer persistent RK4 state (threads 0..63: row rw, batch b) ----
    const int red_r  = tid >> 1;                       // 0..31 (valid for tid<64)
    const int red_b  = tid & 1;
    const int red_rw = blockIdx.x * ROWS_PB + red_r;
    float hbase = 0.f, ksumr = 0.f;
    if (tid < 64) {
        hbase = (red_b ? h_b : h_f)[red_rw];
        // publish initial v = h0 (fp16, L2-resident)
        __stcg(reinterpret_cast<unsigned short*>(&g_vh[red_b][red_rw]),
               __half_as_ushort(__float2half(hbase)));
    }

    // ---- GRU x-half dot (independent of ODE) ----
    for (int j = tid; j < NH; j += TPB) { sm.svf[0][j] = x_f[j]; sm.svf[1][j] = x_b[j]; }
    __syncthreads();
    #pragma unroll
    for (int r2 = 0; r2 < 2; r2++) {
        const int row = blockIdx.x * ROWS_PB + warp * 2 + r2;
        float a0, a1;
        wdot_f2<NH/4>(reinterpret_cast<const float4*>(i2h_W + (size_t)row * K2),
                      reinterpret_cast<const float4*>(sm.svf[0]),
                      reinterpret_cast<const float4*>(sm.svf[1]), lane, a0, a1);
        if (lane == 0) { g_xd[0][row] = a0; g_xd[1][row] = a1; }
    }
    bar_arrive();

    // ---- RK4 ODE: 120 phases ----
    for (int s = 0; s < nsteps; s++) {
        for (int stage = 0; stage < 4; stage++) {
            // ======== layer 1: u = tanh(W1 @ v + b1) ========
            const uint4* A1 = a_ptr(g_W1p, warp, lane);
            a_prefetch(abuf, A1);            // overlaps barrier wait
            bar_wait(target);
            {   // 16 KB .cg copy: g_vh -> smem
                const uint4* src = reinterpret_cast<const uint4*>(&g_vh[0][0]);
                uint4* dst = reinterpret_cast<uint4*>(svh);
                dst[tid]       = __ldcg(src + tid);
                dst[tid + TPB] = __ldcg(src + tid + TPB);
            }
            __syncthreads();
            ode_mma(abuf, A1, svh, sm.part, warp, lane);
            __syncthreads();
            if (tid < 64) {
                float acc = 0.f;
                #pragma unroll
                for (int kc = 0; kc < 8; kc++) acc += sm.part[(kc * 32 + red_r) * 2 + red_b];
                const float u = tanhf(acc + f_b1[red_rw]);
                __stcg(reinterpret_cast<unsigned short*>(&g_uh[red_b][red_rw]),
                       __half_as_ushort(__float2half(u)));
            }
            bar_arrive();

            // ======== layer 2: k = W2 @ u + b2; RK4 state update ========
            const uint4* A2 = a_ptr(g_W2p, warp, lane);
            a_prefetch(abuf, A2);
            bar_wait(target);
            {   // 16 KB .cg copy: g_uh -> smem
                const uint4* src = reinterpret_cast<const uint4*>(&g_uh[0][0]);
                uint4* dst = reinterpret_cast<uint4*>(svh);
                dst[tid]       = __ldcg(src + tid);
                dst[tid + TPB] = __ldcg(src + tid + TPB);
            }
            __syncthreads();
            ode_mma(abuf, A2, svh, sm.part, warp, lane);
            __syncthreads();
            if (tid < 64) {
                float acc = 0.f;
                #pragma unroll
                for (int kc = 0; kc < 8; kc++) acc += sm.part[(kc * 32 + red_r) * 2 + red_b];
                const float kv = acc + f_b2[red_rw];
                const float* t = red_b ? tb : tf;
                const float dt = t[s+1] - t[s];
                float vnext;
                if (stage == 0)      { ksumr = kv;            vnext = hbase + 0.5f*dt*kv; }
                else if (stage == 1) { ksumr += 2.f*kv;       vnext = hbase + 0.5f*dt*kv; }
                else if (stage == 2) { ksumr += 2.f*kv;       vnext = hbase + dt*kv; }
                else {
                    ksumr += kv;
                    hbase += (dt * (1.0f/6.0f)) * ksumr;
                    vnext = hbase;
                    if (s == nsteps - 1)
                        __stcg(&g_vfin[red_b][red_rw], hbase);
                }
                __stcg(reinterpret_cast<unsigned short*>(&g_vh[red_b][red_rw]),
                       __half_as_ushort(__float2half(vnext)));
            }
            bar_arrive();
        }
    }

    // ---- GRU phase 0: g = sigmoid(xd + W_h @ h_fin + b) ----
    bar_wait(target);
    {
        const float4* src = reinterpret_cast<const float4*>(&g_vfin[0][0]);
        float4* dst = reinterpret_cast<float4*>(&sm.svf[0][0]);
        #pragma unroll
        for (int r = 0; r < 4; r++) dst[tid + r * TPB] = __ldcg(src + tid + r * TPB);
    }
    __syncthreads();
    #pragma unroll
    for (int r2 = 0; r2 < 2; r2++) {
        const int row = blockIdx.x * ROWS_PB + warp * 2 + r2;
        float a0, a1;
        wdot_f2<NH/4>(reinterpret_cast<const float4*>(i2h_W + (size_t)row * K2 + NH),
                      reinterpret_cast<const float4*>(sm.svf[0]),
                      reinterpret_cast<const float4*>(sm.svf[1]), lane, a0, a1);
        if (lane == 0) {
            const float bb = i2h_b[row];
            __stcg(&g_g[0][row], 1.f / (1.f + expf(-(g_xd[0][row] + a0 + bb))));
            __stcg(&g_g[1][row], 1.f / (1.f + expf(-(g_xd[1][row] + a1 + bb))));
        }
    }
    bar_arrive();

    // ---- GRU phase 1: h_hat = tanh(xd + W_h @ (g .* h_fin) + b) ----
    bar_wait(target);
    #pragma unroll
    for (int b = 0; b < 2; b++)
        for (int j = tid; j < NH; j += TPB)
            sm.svf[b][j] = __ldcg(&g_g[b][j]) * __ldcg(&g_vfin[b][j]);
    __syncthreads();
    #pragma unroll
    for (int r2 = 0; r2 < 2; r2++) {
        const int row = blockIdx.x * ROWS_PB + warp * 2 + r2;
        float a0, a1;
        wdot_f2<NH/4>(reinterpret_cast<const float4*>(i2h_W + (size_t)row * K2 + NH),
                      reinterpret_cast<const float4*>(sm.svf[0]),
                      reinterpret_cast<const float4*>(sm.svf[1]), lane, a0, a1);
        if (lane == 0) {
            const float bb = i2h_b[row];
            __stcg(&g_hhat[0][row], tanhf(g_xd[0][row] + a0 + bb));
            __stcg(&g_hhat[1][row], tanhf(g_xd[1][row] + a1 + bb));
        }
    }
    bar_arrive();

    // ---- GRU blend + emit h_f / h_b ----
    bar_wait(target);
    {
        int i = blockIdx.x * TPB + tid;
        if (i < 2 * NH) {
            const int b = i >> 12, j = i & (NH - 1);
            const float g  = __ldcg(&g_g[b][j]);
            const float hn = g * __ldcg(&g_vfin[b][j]) + (1.f - g) * __ldcg(&g_hhat[b][j]);
            __stcg(&g_hnew[b][j], hn);
            out[NH + i] = hn;
        }
    }
    bar_arrive();

    // ---- output matvec ----
    bar_wait(target);
    {
        const float4* src = reinterpret_cast<const float4*>(&g_hnew[0][0]);
        float4* dst = reinterpret_cast<float4*>(&sm.svf[0][0]);
        #pragma unroll
        for (int r = 0; r < 4; r++) dst[tid + r * TPB] = __ldcg(src + tid + r * TPB);
    }
    __syncthreads();
    #pragma unroll
    for (int r2 = 0; r2 < 2; r2++) {
        const int row = blockIdx.x * ROWS_PB + warp * 2 + r2;
        float a = wdot_f1<K2/4>(reinterpret_cast<const float4*>(h2o_W + (size_t)row * K2),
                                reinterpret_cast<const float4*>(&sm.svf[0][0]), lane);
        if (lane == 0) out[row] = a + h2o_b[row];
    }
}

extern "C" void kernel_launch(void* const* d_in, const int* in_sizes, int n_in,
                              void* d_out, int out_size)
{
    const float* x_f   = (const float*)d_in[0];
    const float* x_b   = (const float*)d_in[1];
    const float* h_f   = (const float*)d_in[2];
    const float* h_b   = (const float*)d_in[3];
    const float* t_f   = (const float*)d_in[4];
    const float* t_b   = (const float*)d_in[5];
    const float* i2h_W = (const float*)d_in[6];
    const float* i2h_b = (const float*)d_in[7];
    const float* h2o_W = (const float*)d_in[8];
    const float* h2o_b = (const float*)d_in[9];
    const float* f_W1  = (const float*)d_in[10];
    const float* f_b1  = (const float*)d_in[11];
    const float* f_W2  = (const float*)d_in[12];
    const float* f_b2  = (const float*)d_in[13];
    float* out = (float*)d_out;

    const int T = in_sizes[4];
    const int nsteps = T - 1;

    __half *w1p, *w2p;
    cudaGetSymbolAddress((void**)&w1p, g_W1p);
    cudaGetSymbolAddress((void**)&w2p, g_W2p);

    const int permBlocks = (NH / 16) * (NH / 16) * 32 / 256;   // 8192
    k_perm<<<permBlocks, 256>>>(f_W1, w1p);
    k_perm<<<permBlocks, 256>>>(f_W2, w2p);
    k_reset<<<1, 1>>>();

    k_all<<<GRIDB, TPB>>>(f_b1, f_b2, i2h_W, i2h_b, h2o_W, h2o_b,
                          x_f, x_b, h_f, h_b, t_f, t_b, out, nsteps);
}